// round 1
// baseline (speedup 1.0000x reference)
#include <cuda_runtime.h>
#include <math_constants.h>

// Problem constants
#define Bq   8
#define Nq   8192
#define Sq   2048
#define D1q  256
#define D2q  256
#define Pq   (Bq * Nq)   // 65536 points total
#define NSLOT 512        // gridX(64) * B(8) partial-stat slots per channel

// ---------------- scratch (device globals; no allocations allowed) ----------
__device__ float g_X0 [(size_t)Bq * 512 * Nq];   // concat input / reused as Y1
__device__ float g_Y0 [(size_t)Bq * 512 * Nq];   // layer0 raw output
__device__ float g_p2t[(size_t)Bq * Sq * D2q];   // points2 transposed [B,S,D2]
__device__ int   g_idx3[(size_t)Bq * Nq * 3];
__device__ float g_w3  [(size_t)Bq * Nq * 3];
__device__ float g_psum[512 * NSLOT];
__device__ float g_psq [512 * NSLOT];
__device__ float g_scale[3 * 512];
__device__ float g_shift[3 * 512];

// ---------------- transpose points2: [B,D2,S] -> [B,S,D2] -------------------
__global__ void transpose_p2(const float* __restrict__ p2, float* __restrict__ p2t) {
    __shared__ float t[32][33];
    int b  = blockIdx.z;
    int s0 = blockIdx.x * 32;
    int d0 = blockIdx.y * 32;
    int tx = threadIdx.x, ty = threadIdx.y;   // 32 x 8
    const float* src = p2  + (size_t)b * D2q * Sq;
    float*       dst = g_p2t + (size_t)b * Sq * D2q;
    (void)p2t;
#pragma unroll
    for (int i = 0; i < 4; i++) {
        int d = d0 + ty + i * 8;
        t[ty + i * 8][tx] = src[(size_t)d * Sq + s0 + tx];
    }
    __syncthreads();
#pragma unroll
    for (int i = 0; i < 4; i++) {
        int s = s0 + ty + i * 8;
        dst[(size_t)s * D2q + d0 + tx] = t[tx][ty + i * 8];
    }
}

// ---------------- 3-NN + inverse-distance weights ----------------------------
__global__ void knn3_kernel(const float* __restrict__ xyz1, const float* __restrict__ xyz2) {
    __shared__ float sx[Sq], sy[Sq], sz[Sq], sn[Sq];
    int b   = blockIdx.y;
    int tid = threadIdx.x;
    const float* x2 = xyz2 + (size_t)b * 3 * Sq;
    for (int s = tid; s < Sq; s += 128) {
        float X = x2[s], Y = x2[Sq + s], Z = x2[2 * Sq + s];
        sx[s] = X; sy[s] = Y; sz[s] = Z;
        sn[s] = X * X + Y * Y + Z * Z;
    }
    __syncthreads();

    int n = blockIdx.x * 128 + tid;
    const float* x1 = xyz1 + (size_t)b * 3 * Nq;
    float px = x1[n], py = x1[Nq + n], pz = x1[2 * Nq + n];
    float pn = px * px + py * py + pz * pz;

    float d1 = CUDART_INF_F, d2 = CUDART_INF_F, d3 = CUDART_INF_F;
    int   i1 = 0, i2 = 0, i3 = 0;
    for (int s = 0; s < Sq; s++) {
        float dot = px * sx[s] + py * sy[s] + pz * sz[s];
        float d   = pn + sn[s] - 2.0f * dot;   // matches ref formula
        if (d < d3) {
            if (d < d2) {
                if (d < d1) { d3 = d2; i3 = i2; d2 = d1; i2 = i1; d1 = d; i1 = s; }
                else        { d3 = d2; i3 = i2; d2 = d;  i2 = s; }
            } else          { d3 = d;  i3 = s; }
        }
    }
    float r1 = 1.0f / (d1 + 1e-8f);
    float r2 = 1.0f / (d2 + 1e-8f);
    float r3 = 1.0f / (d3 + 1e-8f);
    float rs = r1 + r2 + r3;
    size_t base = ((size_t)b * Nq + n) * 3;
    g_idx3[base] = i1; g_idx3[base + 1] = i2; g_idx3[base + 2] = i3;
    g_w3[base] = r1 / rs; g_w3[base + 1] = r2 / rs; g_w3[base + 2] = r3 / rs;
}

// ---------------- interpolate + concat into X0 [B,512,N] ---------------------
__global__ void interp_concat(const float* __restrict__ p1) {
    __shared__ float t[256][33];
    int b   = blockIdx.y;
    int n0  = blockIdx.x * 32;
    int tid = threadIdx.x;
    const float* p1b  = p1    + (size_t)b * D1q * Nq;
    const float* p2tb = g_p2t + (size_t)b * Sq * D2q;
    float*       x0b  = g_X0  + (size_t)b * 512 * Nq;

    // copy points1 channels 0..255 (layout identical, coalesced)
    for (int i = tid; i < 256 * 32; i += 256) {
        int c = i >> 5, nn = i & 31;
        x0b[(size_t)c * Nq + n0 + nn] = p1b[(size_t)c * Nq + n0 + nn];
    }
    // interpolation for 32 points, 256 channels each
    for (int nn = 0; nn < 32; nn++) {
        size_t base = ((size_t)b * Nq + n0 + nn) * 3;
        int   i0 = g_idx3[base], i1 = g_idx3[base + 1], i2 = g_idx3[base + 2];
        float w0 = g_w3[base], w1 = g_w3[base + 1], w2 = g_w3[base + 2];
        float v = w0 * p2tb[(size_t)i0 * D2q + tid]
                + w1 * p2tb[(size_t)i1 * D2q + tid]
                + w2 * p2tb[(size_t)i2 * D2q + tid];
        t[tid][nn] = v;
    }
    __syncthreads();
    for (int i = tid; i < 256 * 32; i += 256) {
        int c = i >> 5, nn = i & 31;
        x0b[(size_t)(256 + c) * Nq + n0 + nn] = t[c][nn];
    }
}

// ---------------- fused GEMM + BN-stat epilogue ------------------------------
// Y[b][o][n] = sum_c W[o][c] * f(X[b][c][n]),  f = identity or relu(a*x+d)
// also emits deterministic per-CTA partial sum / sumsq per output channel.
template <bool FUSE>
__global__ __launch_bounds__(256, 2)
void gemm_bn(const float* __restrict__ W, const float* __restrict__ X,
             float* __restrict__ Y,
             const float* __restrict__ isc, const float* __restrict__ ish,
             int O, int C) {
    __shared__ float As[8][128];
    __shared__ float Bs[8][128];
    const int b     = blockIdx.z;
    const int oBase = blockIdx.y * 128;
    const int nBase = blockIdx.x * 128;
    const float* Xb = X + (size_t)b * C * Nq;
    float*       Yb = Y + (size_t)b * O * Nq;
    const int tid = threadIdx.x;
    const int tx  = tid & 15, ty = tid >> 4;

    float acc[8][8];
#pragma unroll
    for (int i = 0; i < 8; i++)
#pragma unroll
        for (int j = 0; j < 8; j++) acc[i][j] = 0.0f;

    const int arow = tid >> 1, acolh = (tid & 1) * 4;
    const int brow = tid >> 5, bcol  = (tid & 31) * 4;

    for (int kt = 0; kt < C; kt += 8) {
        float4 av = *(const float4*)&W[(size_t)(oBase + arow) * C + kt + acolh];
        float4 bv = *(const float4*)&Xb[(size_t)(kt + brow) * Nq + nBase + bcol];
        if (FUSE) {
            float a = isc[kt + brow], d = ish[kt + brow];
            bv.x = fmaxf(fmaf(a, bv.x, d), 0.0f);
            bv.y = fmaxf(fmaf(a, bv.y, d), 0.0f);
            bv.z = fmaxf(fmaf(a, bv.z, d), 0.0f);
            bv.w = fmaxf(fmaf(a, bv.w, d), 0.0f);
        }
        As[acolh + 0][arow] = av.x;
        As[acolh + 1][arow] = av.y;
        As[acolh + 2][arow] = av.z;
        As[acolh + 3][arow] = av.w;
        *(float4*)&Bs[brow][bcol] = bv;
        __syncthreads();
#pragma unroll
        for (int k = 0; k < 8; k++) {
            float4 a0 = *(const float4*)&As[k][ty * 4];
            float4 a1 = *(const float4*)&As[k][64 + ty * 4];
            float4 b0 = *(const float4*)&Bs[k][tx * 4];
            float4 b1 = *(const float4*)&Bs[k][64 + tx * 4];
            float ar[8] = {a0.x, a0.y, a0.z, a0.w, a1.x, a1.y, a1.z, a1.w};
            float br[8] = {b0.x, b0.y, b0.z, b0.w, b1.x, b1.y, b1.z, b1.w};
#pragma unroll
            for (int i = 0; i < 8; i++)
#pragma unroll
                for (int j = 0; j < 8; j++)
                    acc[i][j] = fmaf(ar[i], br[j], acc[i][j]);
        }
        __syncthreads();
    }

    const int slot = b * gridDim.x + blockIdx.x;   // < NSLOT, each written once
#pragma unroll
    for (int i = 0; i < 8; i++) {
        int m = oBase + ((i < 4) ? (ty * 4 + i) : (64 + ty * 4 + i - 4));
        float4 s0 = make_float4(acc[i][0], acc[i][1], acc[i][2], acc[i][3]);
        float4 s1 = make_float4(acc[i][4], acc[i][5], acc[i][6], acc[i][7]);
        *(float4*)&Yb[(size_t)m * Nq + nBase + tx * 4]      = s0;
        *(float4*)&Yb[(size_t)m * Nq + nBase + 64 + tx * 4] = s1;

        float s = acc[i][0] + acc[i][1] + acc[i][2] + acc[i][3]
                + acc[i][4] + acc[i][5] + acc[i][6] + acc[i][7];
        float q = acc[i][0] * acc[i][0] + acc[i][1] * acc[i][1]
                + acc[i][2] * acc[i][2] + acc[i][3] * acc[i][3]
                + acc[i][4] * acc[i][4] + acc[i][5] * acc[i][5]
                + acc[i][6] * acc[i][6] + acc[i][7] * acc[i][7];
#pragma unroll
        for (int off = 8; off; off >>= 1) {
            s += __shfl_down_sync(0xffffffffu, s, off, 16);
            q += __shfl_down_sync(0xffffffffu, q, off, 16);
        }
        if (tx == 0) {
            g_psum[(size_t)m * NSLOT + slot] = s;
            g_psq [(size_t)m * NSLOT + slot] = q;
        }
    }
}

// ---------------- BN finalize: per-channel scale/shift -----------------------
__global__ void bn_fin(const float* __restrict__ g, const float* __restrict__ beta,
                       int layer, int O) {
    int o = blockIdx.x * blockDim.x + threadIdx.x;
    if (o >= O) return;
    float s = 0.0f, q = 0.0f;
    for (int j = 0; j < NSLOT; j++) {
        s += g_psum[(size_t)o * NSLOT + j];
        q += g_psq [(size_t)o * NSLOT + j];
    }
    const float invP = 1.0f / (float)Pq;
    float mean = s * invP;
    float var  = q * invP - mean * mean;
    float rstd = rsqrtf(var + 1e-5f);
    float a    = g[o] * rstd;
    g_scale[layer * 512 + o] = a;
    g_shift[layer * 512 + o] = beta[o] - mean * a;
}

// ---------------- final in-place BN+ReLU on d_out ----------------------------
__global__ void finalize_out(float* __restrict__ y) {
    size_t i = (size_t)blockIdx.x * blockDim.x + threadIdx.x;   // float4 index
    float4 v = ((float4*)y)[i];
    int o = (int)((i * 4 / Nq) % 256);
    float a = g_scale[2 * 512 + o], d = g_shift[2 * 512 + o];
    v.x = fmaxf(fmaf(a, v.x, d), 0.0f);
    v.y = fmaxf(fmaf(a, v.y, d), 0.0f);
    v.z = fmaxf(fmaf(a, v.z, d), 0.0f);
    v.w = fmaxf(fmaf(a, v.w, d), 0.0f);
    ((float4*)y)[i] = v;
}

// ---------------- launch -----------------------------------------------------
extern "C" void kernel_launch(void* const* d_in, const int* in_sizes, int n_in,
                              void* d_out, int out_size) {
    const float* xyz1    = (const float*)d_in[0];
    const float* xyz2    = (const float*)d_in[1];
    const float* points1 = (const float*)d_in[2];
    const float* points2 = (const float*)d_in[3];
    const float* w0  = (const float*)d_in[4];
    const float* g0  = (const float*)d_in[6];
    const float* be0 = (const float*)d_in[7];
    const float* w1  = (const float*)d_in[8];
    const float* g1  = (const float*)d_in[10];
    const float* be1 = (const float*)d_in[11];
    const float* w2  = (const float*)d_in[12];
    const float* g2  = (const float*)d_in[14];
    const float* be2 = (const float*)d_in[15];
    float* out = (float*)d_out;

    float *X0, *Y0, *scale, *shift;
    cudaGetSymbolAddress((void**)&X0, g_X0);
    cudaGetSymbolAddress((void**)&Y0, g_Y0);
    cudaGetSymbolAddress((void**)&scale, g_scale);
    cudaGetSymbolAddress((void**)&shift, g_shift);

    // Stage 1: geometry + interpolation + concat
    transpose_p2<<<dim3(Sq / 32, D2q / 32, Bq), dim3(32, 8)>>>(points2, nullptr);
    knn3_kernel<<<dim3(Nq / 128, Bq), 128>>>(xyz1, xyz2);
    interp_concat<<<dim3(Nq / 32, Bq), 256>>>(points1);

    // Stage 2: three fused conv(GEMM) + BN(+ReLU into next layer)
    gemm_bn<false><<<dim3(Nq / 128, 512 / 128, Bq), 256>>>(w0, X0, Y0, nullptr, nullptr, 512, 512);
    bn_fin<<<1, 512>>>(g0, be0, 0, 512);
    gemm_bn<true><<<dim3(Nq / 128, 512 / 128, Bq), 256>>>(w1, Y0, X0, scale + 0, shift + 0, 512, 512);
    bn_fin<<<1, 512>>>(g1, be1, 1, 512);
    gemm_bn<true><<<dim3(Nq / 128, 256 / 128, Bq), 256>>>(w2, X0, out, scale + 512, shift + 512, 256, 512);
    bn_fin<<<1, 256>>>(g2, be2, 2, 256);

    // Stage 3: in-place BN+ReLU on the final output
    finalize_out<<<(Bq * 256 * Nq / 4) / 256, 256>>>(out);
}

// round 4
// speedup vs baseline: 1.7583x; 1.7583x over previous
#include <cuda_runtime.h>
#include <cuda_bf16.h>
#include <cstdint>
#include <math_constants.h>

#define Bq   8
#define Nq   8192
#define Sq   2048
#define Cin  512
#define NTt  128          // n-tile per CTA
#define MTt  128          // o-tile per CTA
#define KC   32           // k chunk
#define NCH  (Cin / KC)   // 16
#define NSLOT 512         // grid.x(64) * B(8)
#define Pq   (Bq * Nq)

// ---------------- scratch (device globals) ----------------------------------
__device__ __align__(16) __nv_bfloat16 g_Xhi[(size_t)Bq * Nq * Cin];
__device__ __align__(16) __nv_bfloat16 g_Xlo[(size_t)Bq * Nq * Cin];
__device__ __align__(16) float         g_Y  [(size_t)Bq * Nq * Cin];
__device__ __align__(16) __nv_bfloat16 g_Whi[655360];   // w0(256K) w1(256K) w2(128K)
__device__ __align__(16) __nv_bfloat16 g_Wlo[655360];
__device__ __align__(16) float g_p2t[(size_t)Bq * Sq * 256];
__device__ int   g_idx3[(size_t)Bq * Nq * 3];
__device__ float g_w3  [(size_t)Bq * Nq * 3];
__device__ float g_psum[512 * NSLOT];
__device__ float g_psq [512 * NSLOT];
__device__ __align__(16) float g_scale[3 * 512];
__device__ __align__(16) float g_shift[3 * 512];

// ---------------- helpers ----------------------------------------------------
__device__ __forceinline__ uint32_t smem_u32(const void* p) {
    uint32_t a;
    asm("{ .reg .u64 t; cvta.to.shared.u64 t, %1; cvt.u32.u64 %0, t; }"
        : "=r"(a) : "l"(p));
    return a;
}
#define SW64(off) ((off) ^ (((off) >> 3) & 0x30))
#define CP_ASYNC16(dst, src) \
    asm volatile("cp.async.cg.shared.global [%0], [%1], 16;" \
                 :: "r"(dst), "l"(src) : "memory")
#define CP_COMMIT()  asm volatile("cp.async.commit_group;" ::: "memory")
#define CP_WAIT(n)   asm volatile("cp.async.wait_group %0;" :: "n"(n) : "memory")

__device__ __forceinline__ void ldsm4(uint32_t* r, uint32_t addr) {
    asm volatile("ldmatrix.sync.aligned.m8n8.x4.shared.b16 {%0,%1,%2,%3}, [%4];"
                 : "=r"(r[0]), "=r"(r[1]), "=r"(r[2]), "=r"(r[3]) : "r"(addr));
}
// B operand: X tile is [n][k] with k contiguous -> plain (non-trans) ldmatrix
// yields the m16n8k16 B fragment directly.  (.trans here was the R3 bug.)
__device__ __forceinline__ void ldsm2(uint32_t* r, uint32_t addr) {
    asm volatile("ldmatrix.sync.aligned.m8n8.x2.shared.b16 {%0,%1}, [%2];"
                 : "=r"(r[0]), "=r"(r[1]) : "r"(addr));
}
__device__ __forceinline__ void mma16816(float* d, const uint32_t* a, const uint32_t* b) {
    asm volatile("mma.sync.aligned.m16n8k16.row.col.f32.bf16.bf16.f32 "
                 "{%0,%1,%2,%3}, {%4,%5,%6,%7}, {%8,%9}, {%0,%1,%2,%3};"
                 : "+f"(d[0]), "+f"(d[1]), "+f"(d[2]), "+f"(d[3])
                 : "r"(a[0]), "r"(a[1]), "r"(a[2]), "r"(a[3]),
                   "r"(b[0]), "r"(b[1]));
}

// ---------------- transpose points2: [B,D2,S] -> [B,S,D2] -------------------
__global__ void transpose_p2(const float* __restrict__ p2) {
    __shared__ float t[32][33];
    int b  = blockIdx.z;
    int s0 = blockIdx.x * 32;
    int d0 = blockIdx.y * 32;
    int tx = threadIdx.x, ty = threadIdx.y;
    const float* src = p2 + (size_t)b * 256 * Sq;
    float*       dst = g_p2t + (size_t)b * Sq * 256;
#pragma unroll
    for (int i = 0; i < 4; i++)
        t[ty + i * 8][tx] = src[(size_t)(d0 + ty + i * 8) * Sq + s0 + tx];
    __syncthreads();
#pragma unroll
    for (int i = 0; i < 4; i++)
        dst[(size_t)(s0 + ty + i * 8) * 256 + d0 + tx] = t[tx][ty + i * 8];
}

// ---------------- 3-NN + inverse-distance weights ----------------------------
__global__ void knn3_kernel(const float* __restrict__ xyz1, const float* __restrict__ xyz2) {
    __shared__ float sx[Sq], sy[Sq], sz[Sq], sn[Sq];
    int b   = blockIdx.y;
    int tid = threadIdx.x;
    const float* x2 = xyz2 + (size_t)b * 3 * Sq;
    for (int s = tid; s < Sq; s += 128) {
        float X = x2[s], Y = x2[Sq + s], Z = x2[2 * Sq + s];
        sx[s] = X; sy[s] = Y; sz[s] = Z;
        sn[s] = X * X + Y * Y + Z * Z;
    }
    __syncthreads();
    int n = blockIdx.x * 128 + tid;
    const float* x1 = xyz1 + (size_t)b * 3 * Nq;
    float px = x1[n], py = x1[Nq + n], pz = x1[2 * Nq + n];
    float pn = px * px + py * py + pz * pz;
    float d1 = CUDART_INF_F, d2 = CUDART_INF_F, d3 = CUDART_INF_F;
    int   i1 = 0, i2 = 0, i3 = 0;
    for (int s = 0; s < Sq; s++) {
        float dot = px * sx[s] + py * sy[s] + pz * sz[s];
        float d   = pn + sn[s] - 2.0f * dot;
        if (d < d3) {
            if (d < d2) {
                if (d < d1) { d3 = d2; i3 = i2; d2 = d1; i2 = i1; d1 = d; i1 = s; }
                else        { d3 = d2; i3 = i2; d2 = d;  i2 = s; }
            } else          { d3 = d;  i3 = s; }
        }
    }
    float r1 = 1.0f / (d1 + 1e-8f);
    float r2 = 1.0f / (d2 + 1e-8f);
    float r3 = 1.0f / (d3 + 1e-8f);
    float rs = r1 + r2 + r3;
    size_t base = ((size_t)b * Nq + n) * 3;
    g_idx3[base] = i1; g_idx3[base + 1] = i2; g_idx3[base + 2] = i3;
    g_w3[base] = r1 / rs; g_w3[base + 1] = r2 / rs; g_w3[base + 2] = r3 / rs;
}

// ---------------- interpolate + concat into bf16 planes [B,N,512] ------------
__global__ void interp_concat(const float* __restrict__ p1) {
    __shared__ float t[32][33];
    int b   = blockIdx.y;
    int n0  = blockIdx.x * 32;
    int tid = threadIdx.x;
    int tx  = tid & 31, ty = tid >> 5;
    const float* p1b = p1 + (size_t)b * 256 * Nq;
    __nv_bfloat16* hi = g_Xhi + (size_t)b * Nq * Cin;
    __nv_bfloat16* lo = g_Xlo + (size_t)b * Nq * Cin;

    for (int ct = 0; ct < 8; ct++) {
        int c0 = ct * 32;
#pragma unroll
        for (int i = 0; i < 4; i++)
            t[ty + 8 * i][tx] = p1b[(size_t)(c0 + ty + 8 * i) * Nq + n0 + tx];
        __syncthreads();
#pragma unroll
        for (int i = 0; i < 4; i++) {
            int n = n0 + ty + 8 * i;
            float v = t[tx][ty + 8 * i];
            __nv_bfloat16 h = __float2bfloat16(v);
            hi[(size_t)n * Cin + c0 + tx] = h;
            lo[(size_t)n * Cin + c0 + tx] = __float2bfloat16(v - __bfloat162float(h));
        }
        __syncthreads();
    }
    const float* p2tb = g_p2t + (size_t)b * Sq * 256;
    for (int nn = 0; nn < 32; nn++) {
        size_t base = ((size_t)b * Nq + n0 + nn) * 3;
        int   j0 = g_idx3[base], j1 = g_idx3[base + 1], j2 = g_idx3[base + 2];
        float w0 = g_w3[base], w1 = g_w3[base + 1], w2 = g_w3[base + 2];
        float v = w0 * p2tb[(size_t)j0 * 256 + tid]
                + w1 * p2tb[(size_t)j1 * 256 + tid]
                + w2 * p2tb[(size_t)j2 * 256 + tid];
        __nv_bfloat16 h = __float2bfloat16(v);
        size_t off = (size_t)(n0 + nn) * Cin + 256 + tid;
        hi[off] = h;
        lo[off] = __float2bfloat16(v - __bfloat162float(h));
    }
}

// ---------------- weight fp32 -> bf16 hi/lo split ----------------------------
__global__ void wsplit(const float* __restrict__ w, __nv_bfloat16* __restrict__ hi,
                       __nv_bfloat16* __restrict__ lo, int n) {
    int i = blockIdx.x * 256 + threadIdx.x;
    if (i >= n) return;
    float v = w[i];
    __nv_bfloat16 h = __float2bfloat16(v);
    hi[i] = h;
    lo[i] = __float2bfloat16(v - __bfloat162float(h));
}

// ---------------- bf16x3 mma.sync GEMM + BN-stat epilogue --------------------
// D[o,n] = sum_c W[o,c] * X[n,c]; Y written [B,N,O] fp32 + per-CTA partials.
// SMEM: stage s (s=0,1) at s*32768: Ahi(8K) Alo(8K) Bhi(8K) Blo(8K).
// Epilogue reuses [0,67584) as float tile[128][132]; red arrays after.
__global__ __launch_bounds__(256, 2)
void gemm_mma(const __nv_bfloat16* __restrict__ Whi, const __nv_bfloat16* __restrict__ Wlo,
              const __nv_bfloat16* __restrict__ Xhi, const __nv_bfloat16* __restrict__ Xlo,
              float* __restrict__ Y, int O) {
    extern __shared__ char smem[];
    const int tid  = threadIdx.x;
    const int wid  = tid >> 5;
    const int lane = tid & 31;
    const int b     = blockIdx.z;
    const int nBase = blockIdx.x * NTt;
    const int oBase = blockIdx.y * MTt;
    const uint32_t sb = smem_u32(smem);

    const __nv_bfloat16* Xhib = Xhi + (size_t)b * Nq * Cin;
    const __nv_bfloat16* Xlob = Xlo + (size_t)b * Nq * Cin;

    // warp tile: 64(m) x 32(n)
    const int wm0 = (wid >> 2) * 64;
    const int wn0 = (wid & 3) * 32;

    float acc[16][4];
#pragma unroll
    for (int i = 0; i < 16; i++)
#pragma unroll
        for (int j = 0; j < 4; j++) acc[i][j] = 0.0f;

    // per-thread cp.async source/dest (2 iters cover 128 rows x 4 16B cols)
    auto load_chunk = [&](int kt, int s) {
        uint32_t st = sb + s * 32768;
#pragma unroll
        for (int i = 0; i < 2; i++) {
            int idx = tid + i * 256;
            int row = idx >> 2, c = idx & 3;
            uint32_t off = (uint32_t)(row * 64 + c * 16);
            uint32_t sw  = SW64(off);
            const __nv_bfloat16* gA  = Whi  + (size_t)(oBase + row) * Cin + kt + c * 8;
            const __nv_bfloat16* gAl = Wlo  + (size_t)(oBase + row) * Cin + kt + c * 8;
            const __nv_bfloat16* gB  = Xhib + (size_t)(nBase + row) * Cin + kt + c * 8;
            const __nv_bfloat16* gBl = Xlob + (size_t)(nBase + row) * Cin + kt + c * 8;
            CP_ASYNC16(st + sw,          gA);
            CP_ASYNC16(st + 8192 + sw,   gAl);
            CP_ASYNC16(st + 16384 + sw,  gB);
            CP_ASYNC16(st + 24576 + sw,  gBl);
        }
    };

    // ldmatrix per-lane address components
    const int q  = lane >> 3, lr = lane & 7;
    const int a_row_off  = (q & 1) * 8 + lr;     // A: within m16 tile
    const int a_col_byte = (q >> 1) * 16;        // A: within k16 (bytes)
    const int jj = lane & 15;
    const int b_row_off  = jj & 7;               // B: within n8 tile
    const int b_col_byte = (jj >> 3) * 16;       // B: k split (bytes)

    load_chunk(0, 0);
    CP_COMMIT();

    for (int k = 0; k < NCH; k++) {
        int s = k & 1;
        if (k + 1 < NCH) {
            load_chunk((k + 1) * KC, 1 - s);
            CP_COMMIT();
            CP_WAIT(1);
        } else {
            CP_WAIT(0);
        }
        __syncthreads();

        uint32_t aHi = sb + s * 32768;
        uint32_t aLo = aHi + 8192;
        uint32_t bHi = aHi + 16384;
        uint32_t bLo = aHi + 24576;

#pragma unroll
        for (int kk = 0; kk < KC; kk += 16) {
            uint32_t afH[4][4], afL[4][4];
#pragma unroll
            for (int mi = 0; mi < 4; mi++) {
                int row = wm0 + mi * 16 + a_row_off;
                uint32_t off = (uint32_t)(row * 64 + kk * 2 + a_col_byte);
                uint32_t sw  = SW64(off);
                ldsm4(afH[mi], aHi + sw);
                ldsm4(afL[mi], aLo + sw);
            }
#pragma unroll
            for (int ni = 0; ni < 4; ni++) {
                int row = wn0 + ni * 8 + b_row_off;
                uint32_t off = (uint32_t)(row * 64 + kk * 2 + b_col_byte);
                uint32_t sw  = SW64(off);
                uint32_t bfH[2], bfL[2];
                ldsm2(bfH, bHi + sw);
                ldsm2(bfL, bLo + sw);
#pragma unroll
                for (int mi = 0; mi < 4; mi++) {
                    mma16816(acc[mi * 4 + ni], afH[mi], bfH);
                    mma16816(acc[mi * 4 + ni], afH[mi], bfL);
                    mma16816(acc[mi * 4 + ni], afL[mi], bfH);
                }
            }
        }
        __syncthreads();
    }

    // ---- epilogue: stage tile through SMEM, coalesced store + BN partials ----
    float* tile = (float*)smem;                    // [128][132]
    float* redS = (float*)(smem + 67584);          // [8][128]
    float* redQ = (float*)(smem + 67584 + 4096);   // [8][128]

    const int o_thr = lane >> 2;          // 0..7
    const int n_thr = 2 * (lane & 3);     // 0,2,4,6
#pragma unroll
    for (int mi = 0; mi < 4; mi++) {
#pragma unroll
        for (int ni = 0; ni < 4; ni++) {
            int o0 = wm0 + mi * 16 + o_thr;
            int n0 = wn0 + ni * 8 + n_thr;
            float* d = acc[mi * 4 + ni];
            tile[n0 * 132 + o0]           = d[0];
            tile[(n0 + 1) * 132 + o0]     = d[1];
            tile[n0 * 132 + o0 + 8]       = d[2];
            tile[(n0 + 1) * 132 + o0 + 8] = d[3];
        }
    }
    __syncthreads();

    const int jrow = tid >> 5;            // 0..7
    const int o4   = (tid & 31) * 4;      // 0..124
    float s0 = 0, s1 = 0, s2 = 0, s3 = 0;
    float q0 = 0, q1 = 0, q2 = 0, q3 = 0;
#pragma unroll
    for (int i = 0; i < 16; i++) {
        int n = jrow + i * 8;
        float4 v = *(const float4*)&tile[n * 132 + o4];
        *(float4*)&Y[((size_t)b * Nq + nBase + n) * O + oBase + o4] = v;
        s0 += v.x; s1 += v.y; s2 += v.z; s3 += v.w;
        q0 += v.x * v.x; q1 += v.y * v.y; q2 += v.z * v.z; q3 += v.w * v.w;
    }
    *(float4*)&redS[jrow * 128 + o4] = make_float4(s0, s1, s2, s3);
    *(float4*)&redQ[jrow * 128 + o4] = make_float4(q0, q1, q2, q3);
    __syncthreads();

    if (tid < 128) {
        float S = 0, Q = 0;
#pragma unroll
        for (int j = 0; j < 8; j++) {
            S += redS[j * 128 + tid];
            Q += redQ[j * 128 + tid];
        }
        int slot = b * gridDim.x + blockIdx.x;
        g_psum[(size_t)(oBase + tid) * NSLOT + slot] = S;
        g_psq [(size_t)(oBase + tid) * NSLOT + slot] = Q;
    }
}

// ---------------- BN finalize ------------------------------------------------
__global__ void bn_fin(const float* __restrict__ g, const float* __restrict__ beta,
                       int layer, int O) {
    int o = blockIdx.x * blockDim.x + threadIdx.x;
    if (o >= O) return;
    float s = 0.0f, q = 0.0f;
    for (int j = 0; j < NSLOT; j++) {
        s += g_psum[(size_t)o * NSLOT + j];
        q += g_psq [(size_t)o * NSLOT + j];
    }
    const float invP = 1.0f / (float)Pq;
    float mean = s * invP;
    float var  = q * invP - mean * mean;
    float rstd = rsqrtf(var + 1e-5f);
    float a    = g[o] * rstd;
    g_scale[layer * 512 + o] = a;
    g_shift[layer * 512 + o] = beta[o] - mean * a;
}

// ---------------- BN+ReLU + bf16 split: Y [B,N,512] -> planes ----------------
__global__ void act_convert(const float* __restrict__ y,
                            const float* __restrict__ sc, const float* __restrict__ sh) {
    size_t i4 = (size_t)blockIdx.x * 256 + threadIdx.x;
    float4 v = ((const float4*)y)[i4];
    int o = (int)((i4 * 4) & (Cin - 1));
    float4 a = *(const float4*)(sc + o);
    float4 d = *(const float4*)(sh + o);
    float x0 = fmaxf(fmaf(a.x, v.x, d.x), 0.0f);
    float x1 = fmaxf(fmaf(a.y, v.y, d.y), 0.0f);
    float x2 = fmaxf(fmaf(a.z, v.z, d.z), 0.0f);
    float x3 = fmaxf(fmaf(a.w, v.w, d.w), 0.0f);
    __nv_bfloat16 h0 = __float2bfloat16(x0), h1 = __float2bfloat16(x1);
    __nv_bfloat16 h2 = __float2bfloat16(x2), h3 = __float2bfloat16(x3);
    __nv_bfloat16 l0 = __float2bfloat16(x0 - __bfloat162float(h0));
    __nv_bfloat16 l1 = __float2bfloat16(x1 - __bfloat162float(h1));
    __nv_bfloat16 l2 = __float2bfloat16(x2 - __bfloat162float(h2));
    __nv_bfloat16 l3 = __float2bfloat16(x3 - __bfloat162float(h3));
    ((__nv_bfloat162*)g_Xhi)[2 * i4]     = __halves2bfloat162(h0, h1);
    ((__nv_bfloat162*)g_Xhi)[2 * i4 + 1] = __halves2bfloat162(h2, h3);
    ((__nv_bfloat162*)g_Xlo)[2 * i4]     = __halves2bfloat162(l0, l1);
    ((__nv_bfloat162*)g_Xlo)[2 * i4 + 1] = __halves2bfloat162(l2, l3);
}

// ---------------- final BN+ReLU + transpose to [B,256,N] ---------------------
__global__ void final_out(const float* __restrict__ y, float* __restrict__ out,
                          const float* __restrict__ sc, const float* __restrict__ sh) {
    __shared__ float t[32][33];
    int b = blockIdx.z, n0 = blockIdx.x * 32, c0 = blockIdx.y * 32;
    int tx = threadIdx.x, ty = threadIdx.y;
    const float* yb = y + (size_t)b * Nq * 256;
    float a = sc[c0 + tx], d = sh[c0 + tx];
#pragma unroll
    for (int i = 0; i < 4; i++) {
        int n = n0 + ty + 8 * i;
        float v = yb[(size_t)n * 256 + c0 + tx];
        t[ty + 8 * i][tx] = fmaxf(fmaf(a, v, d), 0.0f);
    }
    __syncthreads();
#pragma unroll
    for (int i = 0; i < 4; i++)
        out[((size_t)b * 256 + c0 + ty + 8 * i) * Nq + n0 + tx] = t[tx][ty + 8 * i];
}

// ---------------- launch -----------------------------------------------------
extern "C" void kernel_launch(void* const* d_in, const int* in_sizes, int n_in,
                              void* d_out, int out_size) {
    const float* xyz1    = (const float*)d_in[0];
    const float* xyz2    = (const float*)d_in[1];
    const float* points1 = (const float*)d_in[2];
    const float* points2 = (const float*)d_in[3];
    const float* w0  = (const float*)d_in[4];
    const float* g0  = (const float*)d_in[6];
    const float* be0 = (const float*)d_in[7];
    const float* w1  = (const float*)d_in[8];
    const float* g1  = (const float*)d_in[10];
    const float* be1 = (const float*)d_in[11];
    const float* w2  = (const float*)d_in[12];
    const float* g2  = (const float*)d_in[14];
    const float* be2 = (const float*)d_in[15];
    float* out = (float*)d_out;

    __nv_bfloat16 *Whi, *Wlo, *Xhi, *Xlo;
    float *Y, *scale, *shift;
    cudaGetSymbolAddress((void**)&Whi, g_Whi);
    cudaGetSymbolAddress((void**)&Wlo, g_Wlo);
    cudaGetSymbolAddress((void**)&Xhi, g_Xhi);
    cudaGetSymbolAddress((void**)&Xlo, g_Xlo);
    cudaGetSymbolAddress((void**)&Y, g_Y);
    cudaGetSymbolAddress((void**)&scale, g_scale);
    cudaGetSymbolAddress((void**)&shift, g_shift);

    const int SMEM_TOTAL = 67584 + 8192;   // tile[128][132] + red arrays (75776 B)
    cudaFuncSetAttribute(gemm_mma, cudaFuncAttributeMaxDynamicSharedMemorySize, SMEM_TOTAL);

    // weight splits
    wsplit<<<(512 * 512 + 255) / 256, 256>>>(w0, Whi,          Wlo,          512 * 512);
    wsplit<<<(512 * 512 + 255) / 256, 256>>>(w1, Whi + 262144, Wlo + 262144, 512 * 512);
    wsplit<<<(256 * 512 + 255) / 256, 256>>>(w2, Whi + 524288, Wlo + 524288, 256 * 512);

    // geometry + interpolation + concat (bf16 planes, [B,N,512])
    transpose_p2<<<dim3(Sq / 32, 256 / 32, Bq), dim3(32, 8)>>>(points2);
    knn3_kernel<<<dim3(Nq / 128, Bq), 128>>>(xyz1, xyz2);
    interp_concat<<<dim3(Nq / 32, Bq), 256>>>(points1);

    // layer 0
    gemm_mma<<<dim3(Nq / NTt, 512 / MTt, Bq), 256, SMEM_TOTAL>>>(Whi, Wlo, Xhi, Xlo, Y, 512);
    bn_fin<<<1, 512>>>(g0, be0, 0, 512);
    act_convert<<<(Bq * Nq * Cin / 4) / 256, 256>>>(Y, scale, shift);
    // layer 1
    gemm_mma<<<dim3(Nq / NTt, 512 / MTt, Bq), 256, SMEM_TOTAL>>>(Whi + 262144, Wlo + 262144, Xhi, Xlo, Y, 512);
    bn_fin<<<1, 512>>>(g1, be1, 1, 512);
    act_convert<<<(Bq * Nq * Cin / 4) / 256, 256>>>(Y, scale + 512, shift + 512);
    // layer 2
    gemm_mma<<<dim3(Nq / NTt, 256 / MTt, Bq), 256, SMEM_TOTAL>>>(Whi + 524288, Wlo + 524288, Xhi, Xlo, Y, 256);
    bn_fin<<<1, 256>>>(g2, be2, 2, 256);
    final_out<<<dim3(Nq / 32, 8, Bq), dim3(32, 8)>>>(Y, out, scale + 1024, shift + 1024);
}

// round 5
// speedup vs baseline: 2.9414x; 1.6729x over previous
#include <cuda_runtime.h>
#include <cuda_bf16.h>
#include <cstdint>
#include <math_constants.h>

#define Bq   8
#define Nq   8192
#define Sq   2048
#define Cin  512
#define NTt  128          // n-tile per CTA
#define MTt  128          // o-tile per CTA
#define KC   32           // k chunk
#define NCH  (Cin / KC)   // 16
#define NSLOT 512         // grid.x(64) * B(8)
#define Pq   (Bq * Nq)

// ---------------- scratch (device globals) ----------------------------------
__device__ __align__(16) __nv_bfloat16 g_Xhi[(size_t)Bq * Nq * Cin];
__device__ __align__(16) __nv_bfloat16 g_Xlo[(size_t)Bq * Nq * Cin];
__device__ __align__(16) float         g_Y  [(size_t)Bq * Nq * Cin];
__device__ __align__(16) __nv_bfloat16 g_Whi[655360];   // w0(256K) w1(256K) w2(128K)
__device__ __align__(16) __nv_bfloat16 g_Wlo[655360];
__device__ __align__(16) float g_p2t[(size_t)Bq * Sq * 256];
__device__ int   g_idx3[(size_t)Bq * Nq * 3];
__device__ float g_w3  [(size_t)Bq * Nq * 3];
__device__ float g_psum[512 * NSLOT];
__device__ float g_psq [512 * NSLOT];
__device__ __align__(16) float g_scale[3 * 512];
__device__ __align__(16) float g_shift[3 * 512];

// ---------------- helpers ----------------------------------------------------
__device__ __forceinline__ uint32_t smem_u32(const void* p) {
    uint32_t a;
    asm("{ .reg .u64 t; cvta.to.shared.u64 t, %1; cvt.u32.u64 %0, t; }"
        : "=r"(a) : "l"(p));
    return a;
}
#define SW64(off) ((off) ^ (((off) >> 3) & 0x30))
#define CP_ASYNC16(dst, src) \
    asm volatile("cp.async.cg.shared.global [%0], [%1], 16;" \
                 :: "r"(dst), "l"(src) : "memory")
#define CP_COMMIT()  asm volatile("cp.async.commit_group;" ::: "memory")
#define CP_WAIT(n)   asm volatile("cp.async.wait_group %0;" :: "n"(n) : "memory")

__device__ __forceinline__ void ldsm4(uint32_t* r, uint32_t addr) {
    asm volatile("ldmatrix.sync.aligned.m8n8.x4.shared.b16 {%0,%1,%2,%3}, [%4];"
                 : "=r"(r[0]), "=r"(r[1]), "=r"(r[2]), "=r"(r[3]) : "r"(addr));
}
// B operand: X tile is [n][k] with k contiguous -> plain (non-trans) ldmatrix.
__device__ __forceinline__ void ldsm2(uint32_t* r, uint32_t addr) {
    asm volatile("ldmatrix.sync.aligned.m8n8.x2.shared.b16 {%0,%1}, [%2];"
                 : "=r"(r[0]), "=r"(r[1]) : "r"(addr));
}
__device__ __forceinline__ void mma16816(float* d, const uint32_t* a, const uint32_t* b) {
    asm volatile("mma.sync.aligned.m16n8k16.row.col.f32.bf16.bf16.f32 "
                 "{%0,%1,%2,%3}, {%4,%5,%6,%7}, {%8,%9}, {%0,%1,%2,%3};"
                 : "+f"(d[0]), "+f"(d[1]), "+f"(d[2]), "+f"(d[3])
                 : "r"(a[0]), "r"(a[1]), "r"(a[2]), "r"(a[3]),
                   "r"(b[0]), "r"(b[1]));
}

// ---------------- transpose points2: [B,D2,S] -> [B,S,D2] -------------------
__global__ void transpose_p2(const float* __restrict__ p2) {
    __shared__ float t[32][33];
    int b  = blockIdx.z;
    int s0 = blockIdx.x * 32;
    int d0 = blockIdx.y * 32;
    int tx = threadIdx.x, ty = threadIdx.y;
    const float* src = p2 + (size_t)b * 256 * Sq;
    float*       dst = g_p2t + (size_t)b * Sq * 256;
#pragma unroll
    for (int i = 0; i < 4; i++)
        t[ty + i * 8][tx] = src[(size_t)(d0 + ty + i * 8) * Sq + s0 + tx];
    __syncthreads();
#pragma unroll
    for (int i = 0; i < 4; i++)
        dst[(size_t)(s0 + ty + i * 8) * 256 + d0 + tx] = t[tx][ty + i * 8];
}

// ---------------- 3-NN + inverse-distance weights ----------------------------
// float4-packed shared tile: one LDS.128 per candidate instead of 4 scalar LDS.
__global__ void knn3_kernel(const float* __restrict__ xyz1, const float* __restrict__ xyz2) {
    __shared__ float4 sp[Sq];
    int b   = blockIdx.y;
    int tid = threadIdx.x;
    const float* x2 = xyz2 + (size_t)b * 3 * Sq;
    for (int s = tid; s < Sq; s += 128) {
        float X = x2[s], Y = x2[Sq + s], Z = x2[2 * Sq + s];
        sp[s] = make_float4(X, Y, Z, X * X + Y * Y + Z * Z);
    }
    __syncthreads();
    int n = blockIdx.x * 128 + tid;
    const float* x1 = xyz1 + (size_t)b * 3 * Nq;
    float px = x1[n], py = x1[Nq + n], pz = x1[2 * Nq + n];
    float pn = px * px + py * py + pz * pz;
    float d1 = CUDART_INF_F, d2 = CUDART_INF_F, d3 = CUDART_INF_F;
    int   i1 = 0, i2 = 0, i3 = 0;
    for (int s = 0; s < Sq; s++) {
        float4 c = sp[s];
        float dot = px * c.x + py * c.y + pz * c.z;
        float d   = pn + c.w - 2.0f * dot;
        if (d < d3) {
            if (d < d2) {
                if (d < d1) { d3 = d2; i3 = i2; d2 = d1; i2 = i1; d1 = d; i1 = s; }
                else        { d3 = d2; i3 = i2; d2 = d;  i2 = s; }
            } else          { d3 = d;  i3 = s; }
        }
    }
    float r1 = 1.0f / (d1 + 1e-8f);
    float r2 = 1.0f / (d2 + 1e-8f);
    float r3 = 1.0f / (d3 + 1e-8f);
    float rs = r1 + r2 + r3;
    size_t base = ((size_t)b * Nq + n) * 3;
    g_idx3[base] = i1; g_idx3[base + 1] = i2; g_idx3[base + 2] = i3;
    g_w3[base] = r1 / rs; g_w3[base + 1] = r2 / rs; g_w3[base + 2] = r3 / rs;
}

// ---------------- interpolate + concat into bf16 planes [B,N,512] ------------
__global__ void interp_concat(const float* __restrict__ p1) {
    __shared__ float t[32][33];
    int b   = blockIdx.y;
    int n0  = blockIdx.x * 32;
    int tid = threadIdx.x;
    int tx  = tid & 31, ty = tid >> 5;
    const float* p1b = p1 + (size_t)b * 256 * Nq;
    __nv_bfloat16* hi = g_Xhi + (size_t)b * Nq * Cin;
    __nv_bfloat16* lo = g_Xlo + (size_t)b * Nq * Cin;

    for (int ct = 0; ct < 8; ct++) {
        int c0 = ct * 32;
#pragma unroll
        for (int i = 0; i < 4; i++)
            t[ty + 8 * i][tx] = p1b[(size_t)(c0 + ty + 8 * i) * Nq + n0 + tx];
        __syncthreads();
#pragma unroll
        for (int i = 0; i < 4; i++) {
            int n = n0 + ty + 8 * i;
            float v = t[tx][ty + 8 * i];
            __nv_bfloat16 h = __float2bfloat16(v);
            hi[(size_t)n * Cin + c0 + tx] = h;
            lo[(size_t)n * Cin + c0 + tx] = __float2bfloat16(v - __bfloat162float(h));
        }
        __syncthreads();
    }
    const float* p2tb = g_p2t + (size_t)b * Sq * 256;
    for (int nn = 0; nn < 32; nn++) {
        size_t base = ((size_t)b * Nq + n0 + nn) * 3;
        int   j0 = g_idx3[base], j1 = g_idx3[base + 1], j2 = g_idx3[base + 2];
        float w0 = g_w3[base], w1 = g_w3[base + 1], w2 = g_w3[base + 2];
        float v = w0 * p2tb[(size_t)j0 * 256 + tid]
                + w1 * p2tb[(size_t)j1 * 256 + tid]
                + w2 * p2tb[(size_t)j2 * 256 + tid];
        __nv_bfloat16 h = __float2bfloat16(v);
        size_t off = (size_t)(n0 + nn) * Cin + 256 + tid;
        hi[off] = h;
        lo[off] = __float2bfloat16(v - __bfloat162float(h));
    }
}

// ---------------- weight fp32 -> bf16 hi/lo split ----------------------------
__global__ void wsplit(const float* __restrict__ w, __nv_bfloat16* __restrict__ hi,
                       __nv_bfloat16* __restrict__ lo, int n) {
    int i = blockIdx.x * 256 + threadIdx.x;
    if (i >= n) return;
    float v = w[i];
    __nv_bfloat16 h = __float2bfloat16(v);
    hi[i] = h;
    lo[i] = __float2bfloat16(v - __bfloat162float(h));
}

// ---------------- bf16x3 mma.sync GEMM + BN-stat epilogue --------------------
// 3-stage cp.async pipeline, ONE __syncthreads per chunk, prefetch dist 2.
// SMEM: stage s (s=0..2) at s*32768: Ahi(8K) Alo(8K) Bhi(8K) Blo(8K).
// Epilogue reuses [0,67584) as float tile[128][132]; red arrays at 98304.
__global__ __launch_bounds__(256, 2)
void gemm_mma(const __nv_bfloat16* __restrict__ Whi, const __nv_bfloat16* __restrict__ Wlo,
              const __nv_bfloat16* __restrict__ Xhi, const __nv_bfloat16* __restrict__ Xlo,
              float* __restrict__ Y, int O) {
    extern __shared__ char smem[];
    const int tid  = threadIdx.x;
    const int wid  = tid >> 5;
    const int lane = tid & 31;
    const int b     = blockIdx.z;
    const int nBase = blockIdx.x * NTt;
    const int oBase = blockIdx.y * MTt;
    const uint32_t sb = smem_u32(smem);

    const __nv_bfloat16* Xhib = Xhi + (size_t)b * Nq * Cin;
    const __nv_bfloat16* Xlob = Xlo + (size_t)b * Nq * Cin;

    // warp tile: 64(m) x 32(n)
    const int wm0 = (wid >> 2) * 64;
    const int wn0 = (wid & 3) * 32;

    float acc[16][4];
#pragma unroll
    for (int i = 0; i < 16; i++)
#pragma unroll
        for (int j = 0; j < 4; j++) acc[i][j] = 0.0f;

    auto load_chunk = [&](int kt, int s) {
        uint32_t st = sb + s * 32768;
#pragma unroll
        for (int i = 0; i < 2; i++) {
            int idx = tid + i * 256;
            int row = idx >> 2, c = idx & 3;
            uint32_t off = (uint32_t)(row * 64 + c * 16);
            uint32_t sw  = SW64(off);
            const __nv_bfloat16* gA  = Whi  + (size_t)(oBase + row) * Cin + kt + c * 8;
            const __nv_bfloat16* gAl = Wlo  + (size_t)(oBase + row) * Cin + kt + c * 8;
            const __nv_bfloat16* gB  = Xhib + (size_t)(nBase + row) * Cin + kt + c * 8;
            const __nv_bfloat16* gBl = Xlob + (size_t)(nBase + row) * Cin + kt + c * 8;
            CP_ASYNC16(st + sw,          gA);
            CP_ASYNC16(st + 8192 + sw,   gAl);
            CP_ASYNC16(st + 16384 + sw,  gB);
            CP_ASYNC16(st + 24576 + sw,  gBl);
        }
    };

    // ldmatrix per-lane address components
    const int q  = lane >> 3, lr = lane & 7;
    const int a_row_off  = (q & 1) * 8 + lr;     // A: within m16 tile
    const int a_col_byte = (q >> 1) * 16;        // A: within k16 (bytes)
    const int jj = lane & 15;
    const int b_row_off  = jj & 7;               // B: within n8 tile
    const int b_col_byte = (jj >> 3) * 16;       // B: k split (bytes)

    load_chunk(0, 0);  CP_COMMIT();
    load_chunk(KC, 1); CP_COMMIT();

    for (int k = 0; k < NCH; k++) {
        if (k < NCH - 1) { CP_WAIT(1); } else { CP_WAIT(0); }
        __syncthreads();      // chunk k resident; all warps done with MMA(k-1)
        if (k + 2 < NCH) {    // safe: stage (k+2)%3 == (k-1)%3, MMA(k-1) done
            load_chunk((k + 2) * KC, (k + 2) % 3);
            CP_COMMIT();
        }
        const int s = k % 3;
        uint32_t aHi = sb + s * 32768;
        uint32_t aLo = aHi + 8192;
        uint32_t bHi = aHi + 16384;
        uint32_t bLo = aHi + 24576;

#pragma unroll
        for (int kk = 0; kk < KC; kk += 16) {
            uint32_t afH[4][4], afL[4][4];
#pragma unroll
            for (int mi = 0; mi < 4; mi++) {
                int row = wm0 + mi * 16 + a_row_off;
                uint32_t off = (uint32_t)(row * 64 + kk * 2 + a_col_byte);
                uint32_t sw  = SW64(off);
                ldsm4(afH[mi], aHi + sw);
                ldsm4(afL[mi], aLo + sw);
            }
#pragma unroll
            for (int ni = 0; ni < 4; ni++) {
                int row = wn0 + ni * 8 + b_row_off;
                uint32_t off = (uint32_t)(row * 64 + kk * 2 + b_col_byte);
                uint32_t sw  = SW64(off);
                uint32_t bfH[2], bfL[2];
                ldsm2(bfH, bHi + sw);
                ldsm2(bfL, bLo + sw);
#pragma unroll
                for (int mi = 0; mi < 4; mi++) {
                    mma16816(acc[mi * 4 + ni], afH[mi], bfH);
                    mma16816(acc[mi * 4 + ni], afH[mi], bfL);
                    mma16816(acc[mi * 4 + ni], afL[mi], bfH);
                }
            }
        }
    }
    __syncthreads();   // protect smem reuse below

    // ---- epilogue: stage tile through SMEM, coalesced store + BN partials ----
    float* tile = (float*)smem;                    // [128][132] = 67584 B
    float* redS = (float*)(smem + 98304);          // [8][128]
    float* redQ = (float*)(smem + 98304 + 4096);   // [8][128]

    const int o_thr = lane >> 2;          // 0..7
    const int n_thr = 2 * (lane & 3);     // 0,2,4,6
#pragma unroll
    for (int mi = 0; mi < 4; mi++) {
#pragma unroll
        for (int ni = 0; ni < 4; ni++) {
            int o0 = wm0 + mi * 16 + o_thr;
            int n0 = wn0 + ni * 8 + n_thr;
            float* d = acc[mi * 4 + ni];
            tile[n0 * 132 + o0]           = d[0];
            tile[(n0 + 1) * 132 + o0]     = d[1];
            tile[n0 * 132 + o0 + 8]       = d[2];
            tile[(n0 + 1) * 132 + o0 + 8] = d[3];
        }
    }
    __syncthreads();

    const int jrow = tid >> 5;            // 0..7
    const int o4   = (tid & 31) * 4;      // 0..124
    float s0 = 0, s1 = 0, s2 = 0, s3 = 0;
    float q0 = 0, q1 = 0, q2 = 0, q3 = 0;
#pragma unroll
    for (int i = 0; i < 16; i++) {
        int n = jrow + i * 8;
        float4 v = *(const float4*)&tile[n * 132 + o4];
        *(float4*)&Y[((size_t)b * Nq + nBase + n) * O + oBase + o4] = v;
        s0 += v.x; s1 += v.y; s2 += v.z; s3 += v.w;
        q0 += v.x * v.x; q1 += v.y * v.y; q2 += v.z * v.z; q3 += v.w * v.w;
    }
    *(float4*)&redS[jrow * 128 + o4] = make_float4(s0, s1, s2, s3);
    *(float4*)&redQ[jrow * 128 + o4] = make_float4(q0, q1, q2, q3);
    __syncthreads();

    if (tid < 128) {
        float S = 0, Q = 0;
#pragma unroll
        for (int j = 0; j < 8; j++) {
            S += redS[j * 128 + tid];
            Q += redQ[j * 128 + tid];
        }
        int slot = b * gridDim.x + blockIdx.x;
        g_psum[(size_t)(oBase + tid) * NSLOT + slot] = S;
        g_psq [(size_t)(oBase + tid) * NSLOT + slot] = Q;
    }
}

// ---------------- BN finalize: one block per channel -------------------------
__global__ void bn_fin(const float* __restrict__ g, const float* __restrict__ beta,
                       int layer) {
    int o = blockIdx.x;
    int t = threadIdx.x;   // 256
    float s = g_psum[(size_t)o * NSLOT + t] + g_psum[(size_t)o * NSLOT + t + 256];
    float q = g_psq [(size_t)o * NSLOT + t] + g_psq [(size_t)o * NSLOT + t + 256];
    __shared__ float ss[8], qq[8];
#pragma unroll
    for (int off = 16; off; off >>= 1) {
        s += __shfl_down_sync(0xffffffffu, s, off);
        q += __shfl_down_sync(0xffffffffu, q, off);
    }
    if ((t & 31) == 0) { ss[t >> 5] = s; qq[t >> 5] = q; }
    __syncthreads();
    if (t == 0) {
        float S = 0, Q = 0;
#pragma unroll
        for (int j = 0; j < 8; j++) { S += ss[j]; Q += qq[j]; }
        const float invP = 1.0f / (float)Pq;
        float mean = S * invP;
        float var  = Q * invP - mean * mean;
        float rstd = rsqrtf(var + 1e-5f);
        float a    = g[o] * rstd;
        g_scale[layer * 512 + o] = a;
        g_shift[layer * 512 + o] = beta[o] - mean * a;
    }
}

// ---------------- BN+ReLU + bf16 split: Y [B,N,512] -> planes ----------------
__global__ void act_convert(const float* __restrict__ y,
                            const float* __restrict__ sc, const float* __restrict__ sh) {
    size_t i4 = (size_t)blockIdx.x * 256 + threadIdx.x;
    float4 v = ((const float4*)y)[i4];
    int o = (int)((i4 * 4) & (Cin - 1));
    float4 a = *(const float4*)(sc + o);
    float4 d = *(const float4*)(sh + o);
    float x0 = fmaxf(fmaf(a.x, v.x, d.x), 0.0f);
    float x1 = fmaxf(fmaf(a.y, v.y, d.y), 0.0f);
    float x2 = fmaxf(fmaf(a.z, v.z, d.z), 0.0f);
    float x3 = fmaxf(fmaf(a.w, v.w, d.w), 0.0f);
    __nv_bfloat16 h0 = __float2bfloat16(x0), h1 = __float2bfloat16(x1);
    __nv_bfloat16 h2 = __float2bfloat16(x2), h3 = __float2bfloat16(x3);
    __nv_bfloat16 l0 = __float2bfloat16(x0 - __bfloat162float(h0));
    __nv_bfloat16 l1 = __float2bfloat16(x1 - __bfloat162float(h1));
    __nv_bfloat16 l2 = __float2bfloat16(x2 - __bfloat162float(h2));
    __nv_bfloat16 l3 = __float2bfloat16(x3 - __bfloat162float(h3));
    ((__nv_bfloat162*)g_Xhi)[2 * i4]     = __halves2bfloat162(h0, h1);
    ((__nv_bfloat162*)g_Xhi)[2 * i4 + 1] = __halves2bfloat162(h2, h3);
    ((__nv_bfloat162*)g_Xlo)[2 * i4]     = __halves2bfloat162(l0, l1);
    ((__nv_bfloat162*)g_Xlo)[2 * i4 + 1] = __halves2bfloat162(l2, l3);
}

// ---------------- final BN+ReLU + transpose to [B,256,N] ---------------------
__global__ void final_out(const float* __restrict__ y, float* __restrict__ out,
                          const float* __restrict__ sc, const float* __restrict__ sh) {
    __shared__ float t[32][33];
    int b = blockIdx.z, n0 = blockIdx.x * 32, c0 = blockIdx.y * 32;
    int tx = threadIdx.x, ty = threadIdx.y;
    const float* yb = y + (size_t)b * Nq * 256;
    float a = sc[c0 + tx], d = sh[c0 + tx];
#pragma unroll
    for (int i = 0; i < 4; i++) {
        int n = n0 + ty + 8 * i;
        float v = yb[(size_t)n * 256 + c0 + tx];
        t[ty + 8 * i][tx] = fmaxf(fmaf(a, v, d), 0.0f);
    }
    __syncthreads();
#pragma unroll
    for (int i = 0; i < 4; i++)
        out[((size_t)b * 256 + c0 + ty + 8 * i) * Nq + n0 + tx] = t[tx][ty + 8 * i];
}

// ---------------- launch -----------------------------------------------------
extern "C" void kernel_launch(void* const* d_in, const int* in_sizes, int n_in,
                              void* d_out, int out_size) {
    const float* xyz1    = (const float*)d_in[0];
    const float* xyz2    = (const float*)d_in[1];
    const float* points1 = (const float*)d_in[2];
    const float* points2 = (const float*)d_in[3];
    const float* w0  = (const float*)d_in[4];
    const float* g0  = (const float*)d_in[6];
    const float* be0 = (const float*)d_in[7];
    const float* w1  = (const float*)d_in[8];
    const float* g1  = (const float*)d_in[10];
    const float* be1 = (const float*)d_in[11];
    const float* w2  = (const float*)d_in[12];
    const float* g2  = (const float*)d_in[14];
    const float* be2 = (const float*)d_in[15];
    float* out = (float*)d_out;

    __nv_bfloat16 *Whi, *Wlo, *Xhi, *Xlo;
    float *Y, *scale, *shift;
    cudaGetSymbolAddress((void**)&Whi, g_Whi);
    cudaGetSymbolAddress((void**)&Wlo, g_Wlo);
    cudaGetSymbolAddress((void**)&Xhi, g_Xhi);
    cudaGetSymbolAddress((void**)&Xlo, g_Xlo);
    cudaGetSymbolAddress((void**)&Y, g_Y);
    cudaGetSymbolAddress((void**)&scale, g_scale);
    cudaGetSymbolAddress((void**)&shift, g_shift);

    const int SMEM_TOTAL = 3 * 32768 + 8192;   // stages + red arrays = 106496 B
    cudaFuncSetAttribute(gemm_mma, cudaFuncAttributeMaxDynamicSharedMemorySize, SMEM_TOTAL);

    // weight splits
    wsplit<<<(512 * 512 + 255) / 256, 256>>>(w0, Whi,          Wlo,          512 * 512);
    wsplit<<<(512 * 512 + 255) / 256, 256>>>(w1, Whi + 262144, Wlo + 262144, 512 * 512);
    wsplit<<<(256 * 512 + 255) / 256, 256>>>(w2, Whi + 524288, Wlo + 524288, 256 * 512);

    // geometry + interpolation + concat (bf16 planes, [B,N,512])
    transpose_p2<<<dim3(Sq / 32, 256 / 32, Bq), dim3(32, 8)>>>(points2);
    knn3_kernel<<<dim3(Nq / 128, Bq), 128>>>(xyz1, xyz2);
    interp_concat<<<dim3(Nq / 32, Bq), 256>>>(points1);

    // layer 0
    gemm_mma<<<dim3(Nq / NTt, 512 / MTt, Bq), 256, SMEM_TOTAL>>>(Whi, Wlo, Xhi, Xlo, Y, 512);
    bn_fin<<<512, 256>>>(g0, be0, 0);
    act_convert<<<(Bq * Nq * Cin / 4) / 256, 256>>>(Y, scale, shift);
    // layer 1
    gemm_mma<<<dim3(Nq / NTt, 512 / MTt, Bq), 256, SMEM_TOTAL>>>(Whi + 262144, Wlo + 262144, Xhi, Xlo, Y, 512);
    bn_fin<<<512, 256>>>(g1, be1, 1);
    act_convert<<<(Bq * Nq * Cin / 4) / 256, 256>>>(Y, scale + 512, shift + 512);
    // layer 2
    gemm_mma<<<dim3(Nq / NTt, 256 / MTt, Bq), 256, SMEM_TOTAL>>>(Whi + 524288, Wlo + 524288, Xhi, Xlo, Y, 256);
    bn_fin<<<256, 256>>>(g2, be2, 2);
    final_out<<<dim3(Nq / 32, 8, Bq), dim3(32, 8)>>>(Y, out, scale + 1024, shift + 1024);
}